// round 1
// baseline (speedup 1.0000x reference)
#include <cuda_runtime.h>

// ---------------------------------------------------------------------------
// PoolOnlyGNN fused kernel, fp32 baseline.
//
// Structure:
//   init_kernel : zero U/D accumulators, detect batch_ind dtype (i32 vs i64)
//   fused_pool  : ONE pass over x [N,128]:
//                   - copy x -> out
//                   - gate_s = x . gate_w[s] + gate_b[s]; e_s = exp(gate_s)
//                   - feat_s = leaky(x @ feat_w[s] + feat_b[s])   (reg-tiled GEMM)
//                   - U[s][g] += e_s * feat_s ; Dn[s][g] += e_s   (segment sums,
//                     batch_ind sorted -> smem slot accumulators + few atomics)
//   transform_step x3 : xg = leaky([U/Dn, xg] @ tr_w[s] + tr_b[s]) + xg
// ---------------------------------------------------------------------------

#define TILE_R 64
#define NSLOT  8
#define MAXG   8192

__device__ float g_U[3 * MAXG * 128];   // unnormalized pooled
__device__ float g_Dn[3 * MAXG];        // softmax denominators
__device__ float g_xgA[MAXG * 128];
__device__ float g_xgB[MAXG * 128];
__device__ int   g_is64;

__device__ __forceinline__ float leaky1(float v) {
    return v >= 0.f ? v : 0.01f * v;
}

__global__ void init_kernel(const int* __restrict__ bptr, int N, int G) {
    long long total = (long long)3 * G * 128;
    long long tid = (long long)blockIdx.x * blockDim.x + threadIdx.x;
    long long stride = (long long)gridDim.x * blockDim.x;
    for (long long i = tid; i < total; i += stride) g_U[i] = 0.f;
    int td = 3 * G;
    for (long long i = tid; i < td; i += stride) g_Dn[i] = 0.f;
    if (blockIdx.x == 0 && threadIdx.x == 0) {
        // batch_ind may be int32 (JAX x64-disabled demotes int64) or int64.
        // Probe an odd int32-word index near the end: int64 high words are 0
        // (values < G), while int32 sorted graph ids near the end are ~G-1 > 0.
        int probe = (N & 1) ? (N - 2) : (N - 1);
        if (probe < 0) probe = 0;
        g_is64 = (bptr[probe] == 0) ? 1 : 0;
    }
}

// Flush a per-thread per-segment partial into the block slot buffer (or
// directly to global if the segment falls outside the slot window).
__device__ __forceinline__ void flush_part(float* aU, float* aD, int s, int b,
                                           int b0, float4 part, float parte,
                                           int lane, int G) {
    int slot = b - b0;
    if (slot < NSLOT) {
        float* dst = aU + slot * 128 + lane * 4;
        atomicAdd(dst + 0, part.x);
        atomicAdd(dst + 1, part.y);
        atomicAdd(dst + 2, part.z);
        atomicAdd(dst + 3, part.w);
        if (lane == 0) atomicAdd(&aD[slot], parte);
    } else {
        float* dstg = &g_U[((long long)s * G + b) * 128 + lane * 4];
        atomicAdd(dstg + 0, part.x);
        atomicAdd(dstg + 1, part.y);
        atomicAdd(dstg + 2, part.z);
        atomicAdd(dstg + 3, part.w);
        if (lane == 0) atomicAdd(&g_Dn[s * G + b], parte);
    }
}

// smem layout (floats):
//   xs   [64*128]   = 8192     x tile
//   Ws   [128*128]  = 16384    feat_w for current step, [k][c]
//   gw   [3*128]    = 384      gate weights
//   eS   [3*64]     = 192      exp(gate) per step per row
//   aU   [NSLOT*128]= 1024     slot accumulators (U)
//   aD   [NSLOT]    = 8        slot accumulators (denom)
//   bS   [64]       = 64 ints  batch id per row
#define SMEM_FLOATS (8192 + 16384 + 384 + 192 + 1024 + 8 + 64)

__global__ void __launch_bounds__(256) fused_pool(
    const float* __restrict__ x, const int* __restrict__ bptr,
    const float* __restrict__ gate_w, const float* __restrict__ gate_b,
    const float* __restrict__ feat_w, const float* __restrict__ feat_b,
    float* __restrict__ x_out, int N, int G) {
    extern __shared__ float sm[];
    float* xs = sm;             // 8192
    float* Ws = sm + 8192;      // 16384
    float* gw = sm + 24576;     // 384
    float* eS = sm + 24960;     // 192
    float* aU = sm + 25152;     // 1024 (+8 for aD contiguous)
    float* aD = sm + 26176;     // 8
    int* bS = (int*)(sm + 26184);  // 64

    const int t = threadIdx.x;
    const int lane = t & 31;
    const int w = t >> 5;  // warp id = row group (8 rows each)
    const long long row0 = (long long)blockIdx.x * TILE_R;
    const int strb = g_is64 ? 2 : 1;

    for (int i = t; i < 384; i += 256) gw[i] = gate_w[i];
    if (t < TILE_R) {
        long long rr = row0 + t;
        if (rr >= N) rr = N - 1;
        bS[t] = bptr[rr * strb];
    }
    __syncthreads();

    const float gb0 = gate_b[0], gb1 = gate_b[1], gb2 = gate_b[2];

    // ---- load x tile (warp i handles row i*8+w), copy to out, compute gates
#pragma unroll
    for (int i = 0; i < 8; i++) {
        int row = i * 8 + w;
        long long grow = row0 + row;
        bool ok = grow < (long long)N;
        float4 v = make_float4(0.f, 0.f, 0.f, 0.f);
        if (ok) v = __ldg(((const float4*)x) + grow * 32 + lane);
        ((float4*)xs)[row * 32 + lane] = v;
        if (ok && x_out) ((float4*)x_out)[grow * 32 + lane] = v;

        float4 q0 = ((const float4*)gw)[0 * 32 + lane];
        float4 q1 = ((const float4*)gw)[1 * 32 + lane];
        float4 q2 = ((const float4*)gw)[2 * 32 + lane];
        float p0 = v.x * q0.x + v.y * q0.y + v.z * q0.z + v.w * q0.w;
        float p1 = v.x * q1.x + v.y * q1.y + v.z * q1.z + v.w * q1.w;
        float p2 = v.x * q2.x + v.y * q2.y + v.z * q2.z + v.w * q2.w;
#pragma unroll
        for (int o = 16; o > 0; o >>= 1) {
            p0 += __shfl_xor_sync(0xffffffffu, p0, o);
            p1 += __shfl_xor_sync(0xffffffffu, p1, o);
            p2 += __shfl_xor_sync(0xffffffffu, p2, o);
        }
        if (lane == 0) {
            eS[0 * 64 + row] = ok ? expf(p0 + gb0) : 0.f;
            eS[1 * 64 + row] = ok ? expf(p1 + gb1) : 0.f;
            eS[2 * 64 + row] = ok ? expf(p2 + gb2) : 0.f;
        }
    }
    __syncthreads();

    const int b0 = bS[0];

    for (int s = 0; s < 3; s++) {
        // stage feat_w[s] and zero slots
        for (int i = t; i < 4096; i += 256)
            ((float4*)Ws)[i] = __ldg(((const float4*)feat_w) + (long long)s * 4096 + i);
        for (int i = t; i < NSLOT * 128 + NSLOT; i += 256) aU[i] = 0.f;
        float4 fb = __ldg(((const float4*)feat_b) + s * 32 + lane);
        __syncthreads();

        // ---- register-tiled GEMM: this thread owns rows w*8..w*8+7,
        //      cols lane*4..lane*4+3
        float4 acc[8];
#pragma unroll
        for (int r = 0; r < 8; r++) acc[r] = make_float4(0.f, 0.f, 0.f, 0.f);

#pragma unroll 2
        for (int k0 = 0; k0 < 128; k0 += 4) {
            float4 w0 = ((const float4*)Ws)[(k0 + 0) * 32 + lane];
            float4 w1 = ((const float4*)Ws)[(k0 + 1) * 32 + lane];
            float4 w2 = ((const float4*)Ws)[(k0 + 2) * 32 + lane];
            float4 w3 = ((const float4*)Ws)[(k0 + 3) * 32 + lane];
#pragma unroll
            for (int r = 0; r < 8; r++) {
                float4 xv = ((const float4*)xs)[(w * 8 + r) * 32 + (k0 >> 2)];
                acc[r].x += xv.x * w0.x; acc[r].y += xv.x * w0.y;
                acc[r].z += xv.x * w0.z; acc[r].w += xv.x * w0.w;
                acc[r].x += xv.y * w1.x; acc[r].y += xv.y * w1.y;
                acc[r].z += xv.y * w1.z; acc[r].w += xv.y * w1.w;
                acc[r].x += xv.z * w2.x; acc[r].y += xv.z * w2.y;
                acc[r].z += xv.z * w2.z; acc[r].w += xv.z * w2.w;
                acc[r].x += xv.w * w3.x; acc[r].y += xv.w * w3.y;
                acc[r].z += xv.w * w3.z; acc[r].w += xv.w * w3.w;
            }
        }

        // ---- epilogue: bias + leaky + e-weighted segment accumulation
        int curb = bS[w * 8];
        float4 part = make_float4(0.f, 0.f, 0.f, 0.f);
        float parte = 0.f;
#pragma unroll
        for (int r = 0; r < 8; r++) {
            int row = w * 8 + r;
            int b = bS[row];
            if (b != curb) {
                flush_part(aU, aD, s, curb, b0, part, parte, lane, G);
                part = make_float4(0.f, 0.f, 0.f, 0.f);
                parte = 0.f;
                curb = b;
            }
            float e = eS[s * 64 + row];
            float4 v;
            v.x = leaky1(acc[r].x + fb.x);
            v.y = leaky1(acc[r].y + fb.y);
            v.z = leaky1(acc[r].z + fb.z);
            v.w = leaky1(acc[r].w + fb.w);
            part.x += e * v.x; part.y += e * v.y;
            part.z += e * v.z; part.w += e * v.w;
            if (lane == 0) parte += e;
        }
        flush_part(aU, aD, s, curb, b0, part, parte, lane, G);
        __syncthreads();

        // ---- block flush slots -> global atomics
        int span = bS[63] - b0 + 1;
        if (span > NSLOT) span = NSLOT;
        for (int i = t; i < span * 128; i += 256) {
            int slot = i >> 7, c = i & 127;
            atomicAdd(&g_U[((long long)s * G + b0 + slot) * 128 + c], aU[i]);
        }
        if (t < span) atomicAdd(&g_Dn[s * G + b0 + t], aD[t]);
        __syncthreads();
    }
}

// xg = leaky([pooled, xg] @ tr_w + tr_b) + xg ; 8 graphs per block
__global__ void __launch_bounds__(128) transform_step(
    const float* __restrict__ U, const float* __restrict__ Dn,
    const float* __restrict__ xg_in, const float* __restrict__ tw,
    const float* __restrict__ tb, float* __restrict__ xg_out, int G) {
    __shared__ float cat[8][256];
    int t = threadIdx.x;
    int g0 = blockIdx.x * 8;
    for (int i = t; i < 8 * 256; i += 128) {
        int gi = i >> 8, k = i & 255;
        int g = g0 + gi;
        float v = 0.f;
        if (g < G) {
            if (k < 128) {
                float d = Dn[g];
                v = d > 0.f ? U[(size_t)g * 128 + k] / d : 0.f;
            } else {
                v = xg_in[(size_t)g * 128 + (k - 128)];
            }
        }
        cat[gi][k] = v;
    }
    __syncthreads();
    float acc[8];
    float bias = tb[t];
#pragma unroll
    for (int gi = 0; gi < 8; gi++) acc[gi] = bias;
#pragma unroll 4
    for (int k = 0; k < 256; k++) {
        float wv = __ldg(tw + k * 128 + t);
#pragma unroll
        for (int gi = 0; gi < 8; gi++) acc[gi] += cat[gi][k] * wv;
    }
#pragma unroll
    for (int gi = 0; gi < 8; gi++) {
        int g = g0 + gi;
        if (g < G)
            xg_out[(size_t)g * 128 + t] = leaky1(acc[gi]) + cat[gi][128 + t];
    }
}

extern "C" void kernel_launch(void* const* d_in, const int* in_sizes, int n_in,
                              void* d_out, int out_size) {
    const float* x   = (const float*)d_in[0];
    const float* xg0 = (const float*)d_in[1];
    const int*   bp  = (const int*)d_in[4];
    // Address weights from the tail: robust whether or not num_graphs is
    // materialized as an input.
    const float* gate_w = (const float*)d_in[n_in - 6];
    const float* gate_b = (const float*)d_in[n_in - 5];
    const float* feat_w = (const float*)d_in[n_in - 4];
    const float* feat_b = (const float*)d_in[n_in - 3];
    const float* tr_w   = (const float*)d_in[n_in - 2];
    const float* tr_b   = (const float*)d_in[n_in - 1];

    int N = in_sizes[0] / 128;
    int G = in_sizes[1] / 128;

    float* out = (float*)d_out;
    float* x_out = 0;
    float* xg_final = out;
    if ((long long)out_size >= (long long)N * 128 + (long long)G * 128) {
        x_out = out;                        // tuple output: (x, xg)
        xg_final = out + (size_t)N * 128;
    }

    cudaFuncSetAttribute(fused_pool, cudaFuncAttributeMaxDynamicSharedMemorySize,
                         SMEM_FLOATS * 4);

    init_kernel<<<256, 256>>>(bp, N, G);

    int nblk = (N + TILE_R - 1) / TILE_R;
    fused_pool<<<nblk, 256, SMEM_FLOATS * 4>>>(x, bp, gate_w, gate_b, feat_w,
                                               feat_b, x_out, N, G);

    float *dU, *dD, *dA, *dB;
    cudaGetSymbolAddress((void**)&dU, g_U);
    cudaGetSymbolAddress((void**)&dD, g_Dn);
    cudaGetSymbolAddress((void**)&dA, g_xgA);
    cudaGetSymbolAddress((void**)&dB, g_xgB);

    int tblk = (G + 7) / 8;
    transform_step<<<tblk, 128>>>(dU, dD, xg0, tr_w, tr_b, dA, G);
    transform_step<<<tblk, 128>>>(dU + (size_t)G * 128, dD + G, dA,
                                  tr_w + 256 * 128, tr_b + 128, dB, G);
    transform_step<<<tblk, 128>>>(dU + (size_t)2 * G * 128, dD + 2 * G, dB,
                                  tr_w + 2 * 256 * 128, tr_b + 2 * 128,
                                  xg_final, G);
}